// round 15
// baseline (speedup 1.0000x reference)
#include <cuda_runtime.h>
#include <cuda_fp16.h>
#include <stdint.h>

// Problem constants: T=4, B=4, N=512, D=512, F=2048, H=8, dh=64
#define ROWS   8192              // T*B*N
#define DMODEL 512
#define FDIM   2048
#define S512   (ROWS*DMODEL/4)   // B*N*D  (per-timestep spatial size)

// ---------------- scratch (allocation-free: __device__ globals) ----------------
__device__ float g_x   [ROWS*DMODEL];      // running residual stream (fp32)
__device__ float g_pre [ROWS*DMODEL];      // pre-activation scratch (width 512)
__device__ float g_pre2[ROWS*FDIM];        // pre-activation scratch (width 2048)
__device__ __half g_as[2*ROWS*DMODEL];     // activation limbs (x)
__device__ __half g_es[2*ROWS*DMODEL];     // activation limbs (enc)
__device__ __half g_qb[ROWS*DMODEL];       // q spikes
__device__ __half g_kb[ROWS*DMODEL];       // k spikes
__device__ __half g_vb[ROWS*DMODEL];       // v spikes
__device__ __half g_tb[ROWS*DMODEL];       // attn-out spikes
__device__ __half g_hb[ROWS*FDIM];         // MLP hidden spikes
// per-weight limb buffers, transposed [N][K], limb1 at offset N*K
__device__ __half g_w_qs[2*DMODEL*DMODEL];
__device__ __half g_w_ks[2*DMODEL*DMODEL];
__device__ __half g_w_vs[2*DMODEL*DMODEL];
__device__ __half g_w_os[2*DMODEL*DMODEL];
__device__ __half g_w_qc[2*DMODEL*DMODEL];
__device__ __half g_w_kc[2*DMODEL*DMODEL];
__device__ __half g_w_vc[2*DMODEL*DMODEL];
__device__ __half g_w_oc[2*DMODEL*DMODEL];
__device__ __half g_w_1 [2*FDIM*DMODEL];
__device__ __half g_w_2 [2*DMODEL*FDIM];

// ---------------- small helpers ----------------
__device__ __forceinline__ uint32_t smem_u32(const void* p) {
    return (uint32_t)__cvta_generic_to_shared(p);
}

// ---------------- split / fused elementwise kernels ----------------
__global__ void copy_split(const float* __restrict__ X, float* __restrict__ gx,
                           __half* __restrict__ a0, __half* __restrict__ a1, int n)
{
    int i = blockIdx.x * blockDim.x + threadIdx.x;
    if (i >= n) return;
    float v = X[i];
    gx[i] = v;
    __half h = __float2half(v);
    a0[i] = h;
    a1[i] = __float2half(v - __half2float(h));
}

__global__ void asplit2(const float* __restrict__ X,
                        __half* __restrict__ a0, __half* __restrict__ a1, int n)
{
    int i = blockIdx.x * blockDim.x + threadIdx.x;
    if (i >= n) return;
    float v = X[i];
    __half h = __float2half(v);
    a0[i] = h;
    a1[i] = __float2half(v - __half2float(h));
}

// batched weight split: z-th 512x512 weight W[K][N] -> limbs transposed [N][K]
struct WBatch { const float* W[8]; __half* w0[8]; };
__global__ void wsplit_b8(WBatch b)
{
    __shared__ float t[32][33];
    const int z   = blockIdx.z;
    const float* W = b.W[z];
    __half* w0 = b.w0[z];
    __half* w1 = w0 + DMODEL * DMODEL;
    const int tid = threadIdx.x;
    const int n0 = blockIdx.x * 32;
    const int k0 = blockIdx.y * 32;
    for (int i = tid; i < 1024; i += 256) {
        int r = i >> 5, c = i & 31;
        t[r][c] = W[(size_t)(k0 + r) * DMODEL + n0 + c];
    }
    __syncthreads();
    for (int i = tid; i < 1024; i += 256) {
        int r = i >> 5, c = i & 31;
        float x = t[c][r];
        __half h = __float2half(x);
        __half m = __float2half(x - __half2float(h));
        size_t o = (size_t)(n0 + r) * DMODEL + k0 + c;
        w0[o] = h; w1[o] = m;
    }
}

// single weight split (for W1, W2)
__global__ void wsplit2(const float* __restrict__ W,
                        __half* __restrict__ w0, __half* __restrict__ w1, int K, int N)
{
    __shared__ float t[32][33];
    const int tid = threadIdx.x;
    const int n0 = blockIdx.x * 32;
    const int k0 = blockIdx.y * 32;
    for (int i = tid; i < 1024; i += 256) {
        int r = i >> 5, c = i & 31;
        t[r][c] = W[(size_t)(k0 + r) * N + n0 + c];
    }
    __syncthreads();
    for (int i = tid; i < 1024; i += 256) {
        int r = i >> 5, c = i & 31;
        float x = t[c][r];
        __half h = __float2half(x);
        __half m = __float2half(x - __half2float(h));
        size_t o = (size_t)(n0 + r) * K + k0 + c;
        w0[o] = h; w1[o] = m;
    }
}

// LIF over T=4: pre fp32 [4,S] -> spikes fp16 [4,S]
__global__ void lif4h(const float* __restrict__ pre, __half* __restrict__ out, int S)
{
    const int i = blockIdx.x * blockDim.x + threadIdx.x;
    if (i >= S) return;
    float vmem = 0.f;
    #pragma unroll
    for (int t = 0; t < 4; t++) {
        float u = (vmem + pre[(size_t)t * S + i]) * 0.5f;
        if (u >= 1.0f) { out[(size_t)t * S + i] = __float2half(1.0f); vmem = 0.0f; }
        else           { out[(size_t)t * S + i] = __float2half(0.0f); vmem = u;    }
    }
}

// LIF + residual add into x, and write fp16 limbs of the new x
__global__ void lif4_add_split(const float* __restrict__ pre, float* __restrict__ x,
                               __half* __restrict__ a0, __half* __restrict__ a1, int S)
{
    const int i = blockIdx.x * blockDim.x + threadIdx.x;
    if (i >= S) return;
    float vmem = 0.f;
    #pragma unroll
    for (int t = 0; t < 4; t++) {
        const size_t idx = (size_t)t * S + i;
        float u = (vmem + pre[idx]) * 0.5f;
        float xn = x[idx];
        if (u >= 1.0f) { xn += 1.0f; vmem = 0.0f; }
        else           { vmem = u; }
        x[idx] = xn;
        __half h = __float2half(xn);
        a0[idx] = h;
        a1[idx] = __float2half(xn - __half2float(h));
    }
}

// LIF + residual add, final result straight to out
__global__ void lif4_add_out(const float* __restrict__ pre, const float* __restrict__ x,
                             float* __restrict__ out, int S)
{
    const int i = blockIdx.x * blockDim.x + threadIdx.x;
    if (i >= S) return;
    float vmem = 0.f;
    #pragma unroll
    for (int t = 0; t < 4; t++) {
        const size_t idx = (size_t)t * S + i;
        float u = (vmem + pre[idx]) * 0.5f;
        float s;
        if (u >= 1.0f) { s = 1.0f; vmem = 0.0f; }
        else           { s = 0.0f; vmem = u; }
        out[idx] = x[idx] + s;
    }
}

// ---------------- GEMM (exact R10 config): 128x128 tile, 256 thr, 3-stage, 2 syncs ----
struct Segs { const __half* a[3]; const __half* w[3]; };

#define DSM 61696    // 3 stages x (A 128x40h + W 128x40h) = 61440 B, + pad

__global__ __launch_bounds__(256) void gemm_u(
    Segs segs, int nseg, const float* __restrict__ bias,
    float* __restrict__ C, int N, int K)
{
    extern __shared__ char dyn[];
    uint32_t base = (smem_u32(dyn) + 15) & ~15u;
    const uint32_t asb = base;
    const uint32_t wsb = base + 30720;

    const int tid  = threadIdx.x;
    const int lane = tid & 31;
    const int warp = tid >> 5;
    const int m0   = blockIdx.y * 128;
    const int n0   = blockIdx.x * 128;

    const int wm = warp >> 2;   // 0..1 -> 64 rows
    const int wn = warp & 3;    // 0..3 -> 32 cols
    const int r  = lane >> 2;
    const int q  = lane & 3;

    const int aRow = (lane & 7) + ((lane >> 3) & 1) * 8;
    const int aCol = (lane >> 4) * 8;
    const int bRow = (lane & 7) + (lane >> 4) * 8;
    const int bCol = ((lane >> 3) & 1) * 8;

    float acc[4][4][4];
    #pragma unroll
    for (int i = 0; i < 4; i++)
        #pragma unroll
        for (int j = 0; j < 4; j++)
            #pragma unroll
            for (int z = 0; z < 4; z++) acc[i][j][z] = 0.f;

    const int ktiles = K >> 5;
    const int TT = nseg * ktiles;

    auto issue = [&](int t) {
        const int buf3 = t % 3;
        const __half* ap = segs.a[t / ktiles];
        const __half* wp = segs.w[t / ktiles];
        const int kk = (t % ktiles) << 5;
        #pragma unroll
        for (int u = 0; u < 2; ++u) {
            const int c   = tid + (u << 8);
            const int row = c >> 2;
            const int col = (c & 3) << 3;  // halves (8 per 16B)
            const __half* sa = ap + (size_t)(m0 + row) * K + kk + col;
            const __half* sw = wp + (size_t)(n0 + row) * K + kk + col;
            const uint32_t da = asb + (uint32_t)(buf3 * 5120 + row * 40 + col) * 2;
            const uint32_t dw = wsb + (uint32_t)(buf3 * 5120 + row * 40 + col) * 2;
            asm volatile("cp.async.cg.shared.global [%0], [%1], 16;" :: "r"(da), "l"(sa));
            asm volatile("cp.async.cg.shared.global [%0], [%1], 16;" :: "r"(dw), "l"(sw));
        }
        asm volatile("cp.async.commit_group;");
    };

    issue(0);
    issue(1);

    for (int tt = 0; tt < TT; ++tt) {
        if (tt == TT - 1) asm volatile("cp.async.wait_group 0;");
        else              asm volatile("cp.async.wait_group 1;");
        __syncthreads();
        if (tt + 2 < TT) issue(tt + 2);

        const int buf3 = tt % 3;
        const uint32_t aT = asb + (uint32_t)(buf3 * 5120) * 2;
        const uint32_t wT = wsb + (uint32_t)(buf3 * 5120) * 2;

        #pragma unroll
        for (int ko = 0; ko < 32; ko += 16) {
            uint32_t af[4][4], bfr[4][2];
            #pragma unroll
            for (int i = 0; i < 4; i++) {
                const uint32_t addr = aT +
                    (uint32_t)((wm * 64 + i * 16 + aRow) * 40 + ko + aCol) * 2;
                asm volatile(
                    "ldmatrix.sync.aligned.m8n8.x4.shared.b16 {%0,%1,%2,%3}, [%4];"
                    : "=r"(af[i][0]), "=r"(af[i][1]), "=r"(af[i][2]), "=r"(af[i][3])
                    : "r"(addr));
            }
            #pragma unroll
            for (int jj = 0; jj < 2; jj++) {
                const uint32_t addr = wT +
                    (uint32_t)((wn * 32 + jj * 16 + bRow) * 40 + ko + bCol) * 2;
                asm volatile(
                    "ldmatrix.sync.aligned.m8n8.x4.shared.b16 {%0,%1,%2,%3}, [%4];"
                    : "=r"(bfr[2*jj][0]), "=r"(bfr[2*jj][1]),
                      "=r"(bfr[2*jj+1][0]), "=r"(bfr[2*jj+1][1])
                    : "r"(addr));
            }
            #pragma unroll
            for (int i = 0; i < 4; i++)
                #pragma unroll
                for (int j = 0; j < 4; j++)
                    asm volatile(
                        "mma.sync.aligned.m16n8k16.row.col.f32.f16.f16.f32 "
                        "{%0,%1,%2,%3}, {%4,%5,%6,%7}, {%8,%9}, {%0,%1,%2,%3};"
                        : "+f"(acc[i][j][0]), "+f"(acc[i][j][1]),
                          "+f"(acc[i][j][2]), "+f"(acc[i][j][3])
                        : "r"(af[i][0]), "r"(af[i][1]), "r"(af[i][2]), "r"(af[i][3]),
                          "r"(bfr[j][0]), "r"(bfr[j][1]));
        }
        __syncthreads();
    }

    // epilogue: bias add + fp32 store
    #pragma unroll
    for (int i = 0; i < 4; i++) {
        const int R0 = m0 + wm * 64 + i * 16 + r;
        #pragma unroll
        for (int j = 0; j < 4; j++) {
            const int C0 = n0 + wn * 32 + j * 8 + 2 * q;
            const float b0 = bias[C0], b1 = bias[C0 + 1];
            float2 o0, o1;
            o0.x = acc[i][j][0] + b0; o0.y = acc[i][j][1] + b1;
            o1.x = acc[i][j][2] + b0; o1.y = acc[i][j][3] + b1;
            *(float2*)&C[(size_t)R0 * N + C0] = o0;
            *(float2*)&C[(size_t)(R0 + 8) * N + C0] = o1;
        }
    }
}

// ---------------- Attention: out = q (kT v) * alpha, binary fp16 spikes ----------------
__device__ __forceinline__ void unp8h(const __half* g, float* dst)
{
    uint4 u = *reinterpret_cast<const uint4*>(g);
    const __half2* p = reinterpret_cast<const __half2*>(&u);
    #pragma unroll
    for (int z = 0; z < 4; z++) {
        float2 f = __half22float2(p[z]);
        dst[2 * z] = f.x; dst[2 * z + 1] = f.y;
    }
}

__global__ __launch_bounds__(256) void attn_kernel(
    const __half* __restrict__ q, const __half* __restrict__ k,
    const __half* __restrict__ v, float* __restrict__ out)
{
    __shared__ float ktv[64][64];
    __shared__ float ks [64][64];
    __shared__ float vs [64][64];

    const int tid     = threadIdx.x;
    const int h       = blockIdx.x & 7;
    const int tb      = blockIdx.x >> 3;
    const int rowbase = tb * 512;
    const int cbase   = h * 64;

    const int d  = tid >> 2;
    const int e0 = (tid & 3) * 16;
    float acc[16];
    #pragma unroll
    for (int j = 0; j < 16; j++) acc[j] = 0.f;

    for (int m0 = 0; m0 < 512; m0 += 64) {
        for (int i = tid; i < 512; i += 256) {
            const int r = i >> 3;
            const int c = (i & 7) * 8;
            const size_t go = (size_t)(rowbase + m0 + r) * 512 + cbase + c;
            unp8h(k + go, &ks[r][c]);
            unp8h(v + go, &vs[r][c]);
        }
        __syncthreads();
        #pragma unroll 4
        for (int mm = 0; mm < 64; mm++) {
            const float kd = ks[mm][d];
            if (kd != 0.f) {
                #pragma unroll
                for (int j = 0; j < 16; j++) acc[j] += vs[mm][e0 + j];
            }
        }
        __syncthreads();
    }
    #pragma unroll
    for (int j = 0; j < 16; j++) ktv[d][e0 + j] = acc[j];
    __syncthreads();

    for (int n0 = 0; n0 < 512; n0 += 64) {
        for (int i = tid; i < 512; i += 256) {
            const int r = i >> 3;
            const int c = (i & 7) * 8;
            unp8h(q + (size_t)(rowbase + n0 + r) * 512 + cbase + c, &ks[r][c]);
        }
        __syncthreads();
        const int rn  = tid >> 2;
        const int ee0 = (tid & 3) * 16;
        float o[16];
        #pragma unroll
        for (int j = 0; j < 16; j++) o[j] = 0.f;
        #pragma unroll 4
        for (int dd = 0; dd < 64; dd++) {
            const float qd = ks[rn][dd];
            if (qd != 0.f) {
                #pragma unroll
                for (int j = 0; j < 16; j++) o[j] += ktv[dd][ee0 + j];
            }
        }
        #pragma unroll
        for (int j = 0; j < 16; j += 4) {
            float4 ov;
            ov.x = o[j + 0] * 0.125f; ov.y = o[j + 1] * 0.125f;
            ov.z = o[j + 2] * 0.125f; ov.w = o[j + 3] * 0.125f;
            *(float4*)&out[(size_t)(rowbase + n0 + rn) * 512 + cbase + ee0 + j] = ov;
        }
        __syncthreads();
    }
}

// ---------------- host-side orchestration (single stream, R10 ordering) ----------------
static void launch_gemm(const __half* a0, const __half* a1, const __half* w,
                        int nseg, const float* bias, float* C, int N, int K)
{
    // nseg==3: fp32-A (h,h)(m,h)(h,m); nseg==2: binary-A (s,h)(s,m)
    Segs s;
    const size_t SW = (size_t)N * K;
    if (nseg == 3) {
        s.a[0] = a0; s.w[0] = w;
        s.a[1] = a1; s.w[1] = w;
        s.a[2] = a0; s.w[2] = w + SW;
    } else {
        s.a[0] = a0; s.w[0] = w;
        s.a[1] = a0; s.w[1] = w + SW;
        s.a[2] = a0; s.w[2] = w;
    }
    cudaFuncSetAttribute(gemm_u, cudaFuncAttributeMaxDynamicSharedMemorySize, DSM);
    gemm_u<<<dim3(N / 128, ROWS / 128), 256, DSM>>>(s, nseg, bias, C, N, K);
}

extern "C" void kernel_launch(void* const* d_in, const int* in_sizes, int n_in,
                              void* d_out, int out_size)
{
    const float* x    = (const float*)d_in[0];
    const float* enc  = (const float*)d_in[1];
    const float* Wq_s = (const float*)d_in[2];  const float* bq_s = (const float*)d_in[3];
    const float* Wk_s = (const float*)d_in[4];  const float* bk_s = (const float*)d_in[5];
    const float* Wv_s = (const float*)d_in[6];  const float* bv_s = (const float*)d_in[7];
    const float* Wo_s = (const float*)d_in[8];  const float* bo_s = (const float*)d_in[9];
    const float* Wq_c = (const float*)d_in[10]; const float* bq_c = (const float*)d_in[11];
    const float* Wk_c = (const float*)d_in[12]; const float* bk_c = (const float*)d_in[13];
    const float* Wv_c = (const float*)d_in[14]; const float* bv_c = (const float*)d_in[15];
    const float* Wo_c = (const float*)d_in[16]; const float* bo_c = (const float*)d_in[17];
    const float* W1   = (const float*)d_in[18]; const float* b1   = (const float*)d_in[19];
    const float* W2   = (const float*)d_in[20]; const float* b2   = (const float*)d_in[21];

    float *gx, *gpre, *gpre2;
    __half *asb, *esb, *qb, *kb, *vb, *tb, *hb;
    __half *w_qs, *w_ks, *w_vs, *w_os, *w_qc, *w_kc, *w_vc, *w_oc, *w_1, *w_2;
    cudaGetSymbolAddress((void**)&gx,    g_x);
    cudaGetSymbolAddress((void**)&gpre,  g_pre);
    cudaGetSymbolAddress((void**)&gpre2, g_pre2);
    cudaGetSymbolAddress((void**)&asb,   g_as);
    cudaGetSymbolAddress((void**)&esb,   g_es);
    cudaGetSymbolAddress((void**)&qb,    g_qb);
    cudaGetSymbolAddress((void**)&kb,    g_kb);
    cudaGetSymbolAddress((void**)&vb,    g_vb);
    cudaGetSymbolAddress((void**)&tb,    g_tb);
    cudaGetSymbolAddress((void**)&hb,    g_hb);
    cudaGetSymbolAddress((void**)&w_qs,  g_w_qs);
    cudaGetSymbolAddress((void**)&w_ks,  g_w_ks);
    cudaGetSymbolAddress((void**)&w_vs,  g_w_vs);
    cudaGetSymbolAddress((void**)&w_os,  g_w_os);
    cudaGetSymbolAddress((void**)&w_qc,  g_w_qc);
    cudaGetSymbolAddress((void**)&w_kc,  g_w_kc);
    cudaGetSymbolAddress((void**)&w_vc,  g_w_vc);
    cudaGetSymbolAddress((void**)&w_oc,  g_w_oc);
    cudaGetSymbolAddress((void**)&w_1,   g_w_1);
    cudaGetSymbolAddress((void**)&w_2,   g_w_2);

    const size_t SD = (size_t)ROWS * DMODEL;
    __half* as0 = asb; __half* as1 = asb + SD;
    __half* es0 = esb; __half* es1 = esb + SD;

    const int nel = ROWS * DMODEL;
    const int lgD = S512 / 256;

    // ---- input + weight preprocessing (batched, hoisted) ----
    copy_split<<<nel / 256, 256>>>(x, gx, as0, as1, nel);
    asplit2<<<nel / 256, 256>>>(enc, es0, es1, nel);

    WBatch wb;
    wb.W[0] = Wq_s; wb.w0[0] = w_qs;
    wb.W[1] = Wk_s; wb.w0[1] = w_ks;
    wb.W[2] = Wv_s; wb.w0[2] = w_vs;
    wb.W[3] = Wo_s; wb.w0[3] = w_os;
    wb.W[4] = Wq_c; wb.w0[4] = w_qc;
    wb.W[5] = Wk_c; wb.w0[5] = w_kc;
    wb.W[6] = Wv_c; wb.w0[6] = w_vc;
    wb.W[7] = Wo_c; wb.w0[7] = w_oc;
    wsplit_b8<<<dim3(16, 16, 8), 256>>>(wb);
    wsplit2<<<dim3(64, 16), 256>>>(W1, w_1, w_1 + (size_t)FDIM*512, DMODEL, FDIM);
    wsplit2<<<dim3(16, 64), 256>>>(W2, w_2, w_2 + (size_t)512*FDIM, FDIM, DMODEL);

    // ---- self-attention block: x = x + ssa(x, x) (R10 ordering) ----
    launch_gemm(as0, as1, w_qs, 3, bq_s, gpre, DMODEL, DMODEL);
    lif4h<<<lgD, 256>>>(gpre, qb, S512);
    launch_gemm(as0, as1, w_ks, 3, bk_s, gpre, DMODEL, DMODEL);
    lif4h<<<lgD, 256>>>(gpre, kb, S512);
    launch_gemm(as0, as1, w_vs, 3, bv_s, gpre, DMODEL, DMODEL);
    lif4h<<<lgD, 256>>>(gpre, vb, S512);
    attn_kernel<<<128, 256>>>(qb, kb, vb, gpre);
    lif4h<<<lgD, 256>>>(gpre, tb, S512);
    launch_gemm(tb, tb, w_os, 2, bo_s, gpre, DMODEL, DMODEL);
    lif4_add_split<<<lgD, 256>>>(gpre, gx, as0, as1, S512);

    // ---- cross-attention block: x = x + ssa(x, enc) ----
    launch_gemm(as0, as1, w_qc, 3, bq_c, gpre, DMODEL, DMODEL);
    lif4h<<<lgD, 256>>>(gpre, qb, S512);
    launch_gemm(es0, es1, w_kc, 3, bk_c, gpre, DMODEL, DMODEL);
    lif4h<<<lgD, 256>>>(gpre, kb, S512);
    launch_gemm(es0, es1, w_vc, 3, bv_c, gpre, DMODEL, DMODEL);
    lif4h<<<lgD, 256>>>(gpre, vb, S512);
    attn_kernel<<<128, 256>>>(qb, kb, vb, gpre);
    lif4h<<<lgD, 256>>>(gpre, tb, S512);
    launch_gemm(tb, tb, w_oc, 2, bo_c, gpre, DMODEL, DMODEL);
    lif4_add_split<<<lgD, 256>>>(gpre, gx, as0, as1, S512);

    // ---- MLP block: x = x + lif(lif(x@W1+b1)@W2+b2) ----
    launch_gemm(as0, as1, w_1, 3, b1, gpre2, FDIM, DMODEL);
    lif4h<<<(ROWS/4)*FDIM / 256, 256>>>(gpre2, hb, (ROWS/4)*FDIM);
    launch_gemm(hb, hb, w_2, 2, b2, gpre, DMODEL, FDIM);
    lif4_add_out<<<lgD, 256>>>(gpre, gx, (float*)d_out, S512);
}